// round 2
// baseline (speedup 1.0000x reference)
#include <cuda_runtime.h>
#include <mma.h>
#include <cstdint>

using namespace nvcuda;

// Shapes: B=4, P=2048 -> T=8192 tokens, D=1024, H=16, KV=8, HD=64, F=4096, E=16, FE=256
#define T_TOK 8192
#define NPOS  2048

// ---------------- scratch (device globals; no allocation allowed) ----------------
__device__ float sc_h [8192*1024];
__device__ float sc_q [8192*1024];
__device__ float sc_k [8192*512];
__device__ float sc_v [8192*512];
__device__ float sc_ao[8192*1024];
__device__ float sc_g [8192*4096];
__device__ float sc_u [8192*4096];
__device__ float sc_cos[2048*32];
__device__ float sc_sin[2048*32];

// ---------------- rmsnorm ----------------
__global__ __launch_bounds__(256)
void rmsnorm_kernel(const float* __restrict__ x, const float* __restrict__ w,
                    float* __restrict__ out)
{
    int t = blockIdx.x;
    const float* xr = x + (size_t)t * 1024;
    float* orow = out + (size_t)t * 1024;
    int tid = threadIdx.x;

    float4 v = *(const float4*)(xr + tid * 4);
    float s = v.x*v.x + v.y*v.y + v.z*v.z + v.w*v.w;
    #pragma unroll
    for (int o = 16; o; o >>= 1) s += __shfl_xor_sync(0xffffffffu, s, o);
    __shared__ float ws[8];
    if ((tid & 31) == 0) ws[tid >> 5] = s;
    __syncthreads();
    if (tid < 8) {
        float t2 = ws[tid];
        #pragma unroll
        for (int o = 4; o; o >>= 1) t2 += __shfl_xor_sync(0xffu, t2, o);
        if (tid == 0) ws[0] = t2;
    }
    __syncthreads();
    float rinv = rsqrtf(ws[0] * (1.0f / 1024.0f) + 1e-6f);
    float4 wv = *(const float4*)(w + tid * 4);
    float4 r;
    r.x = v.x * rinv * wv.x;
    r.y = v.y * rinv * wv.y;
    r.z = v.z * rinv * wv.z;
    r.w = v.w * rinv * wv.w;
    *(float4*)(orow + tid * 4) = r;
}

// ---------------- pipelined TF32 GEMM ----------------
// C[M,N] = A[M,K] @ B[K,N] (+bias/res/accum epilogues)
// Blocked-B addressing: addr(k,n) = B + (n/nbs)*nstride + k*ldb + (n%nbs)
// 3-stage cp.async pipeline, KTILE=32, block tile 128x128, 8 warps of 32x64.
#define GBK   32
#define GLDA  36
#define GLDB  132
#define ASTG  (128 * GLDA)      // floats per A stage
#define BSTG  (GBK * GLDB)      // floats per B stage
#define GSMEM ((3 * (ASTG + BSTG)) * 4)

__device__ __forceinline__ void cp16(uint32_t saddr, const void* g)
{
    asm volatile("cp.async.cg.shared.global [%0], [%1], 16;\n" :: "r"(saddr), "l"(g));
}
#define CP_COMMIT() asm volatile("cp.async.commit_group;\n" ::)
#define CP_WAIT1()  asm volatile("cp.async.wait_group 1;\n" ::)

__global__ __launch_bounds__(256)
void gemm_tf32(const float* __restrict__ A, const float* __restrict__ B,
               float* __restrict__ C, int M, int N, int K,
               int ldb, int nbs, long long nstride,
               const float* __restrict__ bias, const float* __restrict__ res,
               int accum)
{
    extern __shared__ float sm[];
    float* As = sm;               // 3 stages of 128x32 (stride GLDA)
    float* Bs = sm + 3 * ASTG;    // 3 stages of 32x128 (stride GLDB)
    uint32_t smemBase = (uint32_t)__cvta_generic_to_shared(sm);

    int bm = blockIdx.y * 128, bn = blockIdx.x * 128;
    int tid = threadIdx.x, wid = tid >> 5, lane = tid & 31;
    int wm = (wid >> 1) * 32, wn = (wid & 1) * 64;

    // per-thread load coords
    int ar = tid >> 1;                    // A: 128 rows x 2 threads (each 4 float4? no:)
    // A tile: 128 rows x 8 float4 = 1024 float4, 4 per thread
    // thread handles j = tid + it*256 ; r = j>>3, c4 = j&7
    // B tile: 32 rows x 32 float4 = 1024 float4, 4 per thread
    (void)ar;

    wmma::fragment<wmma::accumulator, 16, 16, 8, float> acc[2][4];
    #pragma unroll
    for (int i = 0; i < 2; i++)
        #pragma unroll
        for (int j = 0; j < 4; j++) wmma::fill_fragment(acc[i][j], 0.0f);

    int nk = K / GBK;

    auto prefetch = [&](int s, int k0) {
        uint32_t as = smemBase + (uint32_t)(s * ASTG) * 4;
        uint32_t bs = smemBase + (uint32_t)((3 * ASTG + s * BSTG)) * 4;
        #pragma unroll
        for (int it = 0; it < 4; it++) {
            int j = tid + it * 256;
            int r = j >> 3, c4 = j & 7;
            cp16(as + (uint32_t)(r * GLDA + c4 * 4) * 4,
                 A + (size_t)(bm + r) * K + k0 + c4 * 4);
        }
        #pragma unroll
        for (int it = 0; it < 4; it++) {
            int j = tid + it * 256;
            int r = j >> 5, c4 = j & 31;
            int n = bn + c4 * 4;
            const float* bp = B + (size_t)(n / nbs) * nstride
                                + (size_t)(k0 + r) * ldb + (n % nbs);
            cp16(bs + (uint32_t)(r * GLDB + c4 * 4) * 4, bp);
        }
    };

    // prologue: stages 0 and 1
    prefetch(0, 0);       CP_COMMIT();
    prefetch(1, GBK);     CP_COMMIT();

    for (int i = 0; i < nk; i++) {
        CP_WAIT1();
        __syncthreads();

        int s = i % 3;
        const float* as = As + s * ASTG;
        const float* bs = Bs + s * BSTG;
        #pragma unroll
        for (int kk = 0; kk < GBK; kk += 8) {
            wmma::fragment<wmma::matrix_a, 16, 16, 8, wmma::precision::tf32, wmma::row_major> af[2];
            wmma::fragment<wmma::matrix_b, 16, 16, 8, wmma::precision::tf32, wmma::row_major> bf[4];
            #pragma unroll
            for (int ii = 0; ii < 2; ii++) {
                wmma::load_matrix_sync(af[ii], as + (wm + ii * 16) * GLDA + kk, GLDA);
                #pragma unroll
                for (int e = 0; e < af[ii].num_elements; e++)
                    af[ii].x[e] = wmma::__float_to_tf32(af[ii].x[e]);
            }
            #pragma unroll
            for (int jj = 0; jj < 4; jj++) {
                wmma::load_matrix_sync(bf[jj], bs + kk * GLDB + wn + jj * 16, GLDB);
                #pragma unroll
                for (int e = 0; e < bf[jj].num_elements; e++)
                    bf[jj].x[e] = wmma::__float_to_tf32(bf[jj].x[e]);
            }
            #pragma unroll
            for (int ii = 0; ii < 2; ii++)
                #pragma unroll
                for (int jj = 0; jj < 4; jj++)
                    wmma::mma_sync(acc[ii][jj], af[ii], bf[jj], acc[ii][jj]);
        }

        int next = i + 2;
        if (next < nk) prefetch(next % 3, next * GBK);
        CP_COMMIT();   // always commit (empty groups keep wait_group aligned)
    }

    __syncthreads();  // before reusing smem for epilogue staging

    float* buf = sm + wid * 256;
    #pragma unroll
    for (int i = 0; i < 2; i++)
        for (int j = 0; j < 4; j++) {
            wmma::store_matrix_sync(buf, acc[i][j], 16, wmma::mem_row_major);
            __syncwarp();
            int r0 = bm + wm + i * 16, c0 = bn + wn + j * 16;
            #pragma unroll
            for (int t2 = 0; t2 < 8; t2++) {
                int e = lane * 8 + t2;
                int er = e >> 4, ec = e & 15;
                float vv = buf[e];
                if (bias) vv += bias[c0 + ec];
                size_t ci = (size_t)(r0 + er) * N + (c0 + ec);
                if (res)   vv += res[ci];
                if (accum) vv += C[ci];
                C[ci] = vv;
            }
            __syncwarp();
        }
}

// ---------------- RoPE ----------------
__global__ void rope_table(float* __restrict__ ct, float* __restrict__ st)
{
    int i = blockIdx.x * 256 + threadIdx.x;   // 2048*32
    int p = i >> 5, j = i & 31;
    float inv = powf(10000.0f, -(float)j * (1.0f / 32.0f));
    float ang = (float)p * inv;
    float s, c;
    sincosf(ang, &s, &c);
    ct[i] = c; st[i] = s;
}

__global__ void rope_apply(float* __restrict__ v, int nh,
                           const float* __restrict__ ct, const float* __restrict__ st)
{
    int i = blockIdx.x * 256 + threadIdx.x;
    int tot = T_TOK * nh * 32;
    if (i >= tot) return;
    int j = i & 31;
    int h = (i >> 5) % nh;
    int t = i / (nh * 32);
    int p = t & (NPOS - 1);
    float c = ct[p * 32 + j], s = st[p * 32 + j];
    size_t base = (size_t)t * nh * 64 + h * 64;
    float v1 = v[base + j], v2 = v[base + 32 + j];
    v[base + j]      = v1 * c - v2 * s;
    v[base + 32 + j] = v2 * c + v1 * s;
}

// ---------------- flash attention (causal, GQA 2:1, HD=64) ----------------
#define FLD 72
__global__ __launch_bounds__(256)
void flash_attn(const float* __restrict__ q, const float* __restrict__ k,
                const float* __restrict__ v, float* __restrict__ o)
{
    extern __shared__ float sm[];
    float* Qs = sm;
    float* Ks = Qs + 64 * FLD;
    float* Vs = Ks + 64 * FLD;
    float* Ss = Vs + 64 * FLD;
    float* Os = Ss + 64 * FLD;
    float* mrow = Os + 64 * FLD;
    float* lrow = mrow + 64;
    float* crow = lrow + 64;

    int qt = blockIdx.x, h = blockIdx.y, b = blockIdx.z;
    int tid = threadIdx.x, wid = tid >> 5;
    int kvh = h >> 1;

    const float* qb = q + ((size_t)(b * NPOS + qt * 64)) * 1024 + h * 64;
    for (int i = tid; i < 1024; i += 256) {
        int r = i >> 4, c4 = i & 15;
        float4 val = *(const float4*)(qb + (size_t)r * 1024 + c4 * 4);
        val.x *= 0.125f; val.y *= 0.125f; val.z *= 0.125f; val.w *= 0.125f;
        *(float4*)(Qs + r * FLD + c4 * 4) = val;
    }
    for (int i = tid; i < 4096; i += 256) {
        int r = i >> 6, c = i & 63;
        Os[r * FLD + c] = 0.0f;
    }
    if (tid < 64) { mrow[tid] = -1e30f; lrow[tid] = 0.0f; }
    __syncthreads();

    int wm = (wid >> 1) * 16, wn = (wid & 1) * 32;

    for (int kt = 0; kt <= qt; kt++) {
        const float* kb = k + ((size_t)(b * NPOS + kt * 64)) * 512 + kvh * 64;
        const float* vb = v + ((size_t)(b * NPOS + kt * 64)) * 512 + kvh * 64;
        for (int i = tid; i < 1024; i += 256) {
            int r = i >> 4, c4 = i & 15;
            *(float4*)(Ks + r * FLD + c4 * 4) = *(const float4*)(kb + (size_t)r * 512 + c4 * 4);
            *(float4*)(Vs + r * FLD + c4 * 4) = *(const float4*)(vb + (size_t)r * 512 + c4 * 4);
        }
        __syncthreads();

        {
            wmma::fragment<wmma::accumulator, 16, 16, 8, float> sacc[2];
            wmma::fill_fragment(sacc[0], 0.0f);
            wmma::fill_fragment(sacc[1], 0.0f);
            for (int d = 0; d < 64; d += 8) {
                wmma::fragment<wmma::matrix_a, 16, 16, 8, wmma::precision::tf32, wmma::row_major> af;
                wmma::load_matrix_sync(af, Qs + wm * FLD + d, FLD);
                #pragma unroll
                for (int e = 0; e < af.num_elements; e++) af.x[e] = wmma::__float_to_tf32(af.x[e]);
                #pragma unroll
                for (int j = 0; j < 2; j++) {
                    wmma::fragment<wmma::matrix_b, 16, 16, 8, wmma::precision::tf32, wmma::col_major> bf;
                    wmma::load_matrix_sync(bf, Ks + (wn + j * 16) * FLD + d, FLD);
                    #pragma unroll
                    for (int e = 0; e < bf.num_elements; e++) bf.x[e] = wmma::__float_to_tf32(bf.x[e]);
                    wmma::mma_sync(sacc[j], af, bf, sacc[j]);
                }
            }
            wmma::store_matrix_sync(Ss + wm * FLD + wn,      sacc[0], FLD, wmma::mem_row_major);
            wmma::store_matrix_sync(Ss + wm * FLD + wn + 16, sacc[1], FLD, wmma::mem_row_major);
        }
        __syncthreads();

        {
            int r = tid >> 2, pp = tid & 3;
            int qg = qt * 64 + r;
            float vals[16]; float mx = -1e30f;
            #pragma unroll
            for (int c = 0; c < 16; c++) {
                int col = pp * 16 + c;
                float sv = Ss[r * FLD + col];
                if (kt * 64 + col > qg) sv = -1e30f;
                vals[c] = sv; mx = fmaxf(mx, sv);
            }
            mx = fmaxf(mx, __shfl_xor_sync(0xffffffffu, mx, 1));
            mx = fmaxf(mx, __shfl_xor_sync(0xffffffffu, mx, 2));
            float mold = mrow[r];
            float mnew = fmaxf(mold, mx);
            float sum = 0.0f;
            #pragma unroll
            for (int c = 0; c < 16; c++) {
                float e = __expf(vals[c] - mnew);
                Ss[r * FLD + pp * 16 + c] = e;
                sum += e;
            }
            sum += __shfl_xor_sync(0xffffffffu, sum, 1);
            sum += __shfl_xor_sync(0xffffffffu, sum, 2);
            if (pp == 0) {
                float cc = __expf(mold - mnew);
                lrow[r] = lrow[r] * cc + sum;
                mrow[r] = mnew;
                crow[r] = cc;
            }
        }
        __syncthreads();

        {
            wmma::fragment<wmma::accumulator, 16, 16, 8, float> pv[2];
            wmma::fill_fragment(pv[0], 0.0f);
            wmma::fill_fragment(pv[1], 0.0f);
            for (int kk = 0; kk < 64; kk += 8) {
                wmma::fragment<wmma::matrix_a, 16, 16, 8, wmma::precision::tf32, wmma::row_major> af;
                wmma::load_matrix_sync(af, Ss + wm * FLD + kk, FLD);
                #pragma unroll
                for (int e = 0; e < af.num_elements; e++) af.x[e] = wmma::__float_to_tf32(af.x[e]);
                #pragma unroll
                for (int j = 0; j < 2; j++) {
                    wmma::fragment<wmma::matrix_b, 16, 16, 8, wmma::precision::tf32, wmma::row_major> bf;
                    wmma::load_matrix_sync(bf, Vs + kk * FLD + wn + j * 16, FLD);
                    #pragma unroll
                    for (int e = 0; e < bf.num_elements; e++) bf.x[e] = wmma::__float_to_tf32(bf.x[e]);
                    wmma::mma_sync(pv[j], af, bf, pv[j]);
                }
            }
            wmma::store_matrix_sync(Ks + wm * FLD + wn,      pv[0], FLD, wmma::mem_row_major);
            wmma::store_matrix_sync(Ks + wm * FLD + wn + 16, pv[1], FLD, wmma::mem_row_major);
        }
        __syncthreads();

        for (int i = tid; i < 4096; i += 256) {
            int r = i >> 6, c = i & 63;
            Os[r * FLD + c] = Os[r * FLD + c] * crow[r] + Ks[r * FLD + c];
        }
        __syncthreads();
    }

    float* ob = o + ((size_t)(b * NPOS + qt * 64)) * 1024 + h * 64;
    for (int i = tid; i < 4096; i += 256) {
        int r = i >> 6, c = i & 63;
        ob[(size_t)r * 1024 + c] = Os[r * FLD + c] / lrow[r];
    }
}

// ---------------- SwiGLU (+optional expert-mask fold) ----------------
__global__ void swiglu_kernel(float* __restrict__ g, const float* __restrict__ u,
                              const float* __restrict__ mask)
{
    size_t i = (size_t)blockIdx.x * 256 + threadIdx.x;
    float gv = g[i], uv = u[i];
    float a = gv / (1.0f + __expf(-gv)) * uv;
    if (mask) {
        size_t t = i >> 12;
        int e = (int)((i >> 8) & 15);
        a *= mask[t * 16 + e];
    }
    g[i] = a;
}

// ---------------- launch ----------------
extern "C" void kernel_launch(void* const* d_in, const int* in_sizes, int n_in,
                              void* d_out, int out_size)
{
    const float* x       = (const float*)d_in[0];
    const float* emask   = (const float*)d_in[1];
    const float* ln1     = (const float*)d_in[2];
    const float* wq      = (const float*)d_in[3];
    const float* bq      = (const float*)d_in[4];
    const float* wk      = (const float*)d_in[5];
    const float* bk      = (const float*)d_in[6];
    const float* wv      = (const float*)d_in[7];
    const float* bv      = (const float*)d_in[8];
    const float* wo      = (const float*)d_in[9];
    const float* ln2     = (const float*)d_in[10];
    const float* w_gate  = (const float*)d_in[11];
    const float* w_up    = (const float*)d_in[12];
    const float* w_down  = (const float*)d_in[13];
    const float* we_gate = (const float*)d_in[14];
    const float* we_up   = (const float*)d_in[15];
    const float* we_down = (const float*)d_in[16];
    float* out = (float*)d_out;

    float *h, *qb, *kb, *vb, *ao, *g, *u, *ct, *st;
    cudaGetSymbolAddress((void**)&h,  sc_h);
    cudaGetSymbolAddress((void**)&qb, sc_q);
    cudaGetSymbolAddress((void**)&kb, sc_k);
    cudaGetSymbolAddress((void**)&vb, sc_v);
    cudaGetSymbolAddress((void**)&ao, sc_ao);
    cudaGetSymbolAddress((void**)&g,  sc_g);
    cudaGetSymbolAddress((void**)&u,  sc_u);
    cudaGetSymbolAddress((void**)&ct, sc_cos);
    cudaGetSymbolAddress((void**)&st, sc_sin);

    const int FLASH_SMEM = (5 * 64 * FLD + 3 * 64) * 4;
    cudaFuncSetAttribute(flash_attn, cudaFuncAttributeMaxDynamicSharedMemorySize, FLASH_SMEM);
    cudaFuncSetAttribute(gemm_tf32, cudaFuncAttributeMaxDynamicSharedMemorySize, GSMEM);

    const int M = T_TOK;
    const int NB = 1 << 28;
    dim3 thr(256);

    rmsnorm_kernel<<<M, 256>>>(x, ln1, h);

    gemm_tf32<<<dim3(8, 64), thr, GSMEM>>>(h, wq, qb, M, 1024, 1024, 1024, NB, 0, bq, nullptr, 0);
    gemm_tf32<<<dim3(4, 64), thr, GSMEM>>>(h, wk, kb, M,  512, 1024,  512, NB, 0, bk, nullptr, 0);
    gemm_tf32<<<dim3(4, 64), thr, GSMEM>>>(h, wv, vb, M,  512, 1024,  512, NB, 0, bv, nullptr, 0);

    rope_table<<<256, 256>>>(ct, st);
    rope_apply<<<16384, 256>>>(qb, 16, ct, st);
    rope_apply<<< 8192, 256>>>(kb,  8, ct, st);

    flash_attn<<<dim3(32, 16, 4), 256, FLASH_SMEM>>>(qb, kb, vb, ao);

    gemm_tf32<<<dim3(8, 64), thr, GSMEM>>>(ao, wo, out, M, 1024, 1024, 1024, NB, 0, nullptr, x, 0);

    rmsnorm_kernel<<<M, 256>>>(out, ln2, h);

    gemm_tf32<<<dim3(32, 64), thr, GSMEM>>>(h, w_gate, g, M, 4096, 1024, 4096, NB, 0, nullptr, nullptr, 0);
    gemm_tf32<<<dim3(32, 64), thr, GSMEM>>>(h, w_up,   u, M, 4096, 1024, 4096, NB, 0, nullptr, nullptr, 0);
    swiglu_kernel<<<131072, 256>>>(g, u, nullptr);
    gemm_tf32<<<dim3(8, 64), thr, GSMEM>>>(g, w_down, out, M, 1024, 4096, 1024, NB, 0, nullptr, nullptr, 1);

    gemm_tf32<<<dim3(32, 64), thr, GSMEM>>>(h, we_gate, g, M, 4096, 1024, 256, 256, 1024LL * 256, nullptr, nullptr, 0);
    gemm_tf32<<<dim3(32, 64), thr, GSMEM>>>(h, we_up,   u, M, 4096, 1024, 256, 256, 1024LL * 256, nullptr, nullptr, 0);
    swiglu_kernel<<<131072, 256>>>(g, u, emask);
    gemm_tf32<<<dim3(8, 64), thr, GSMEM>>>(g, we_down, out, M, 1024, 4096, 1024, NB, 0, nullptr, nullptr, 1);
}

// round 3
// speedup vs baseline: 3.5162x; 3.5162x over previous
#include <cuda_runtime.h>
#include <cuda_fp16.h>
#include <mma.h>
#include <cstdint>

using namespace nvcuda;

// Shapes: B=4, P=2048 -> T=8192 tokens, D=1024, H=16, KV=8, HD=64, F=4096, E=16, FE=256
#define T_TOK 8192
#define NPOS  2048

// ---------------- scratch (device globals) ----------------
__device__ __half sc_hh [8192*1024];     // rmsnorm out (fp16)
__device__ float  sc_q  [8192*1024];
__device__ float  sc_k  [8192*512];
__device__ float  sc_v  [8192*512];
__device__ __half sc_aoh[8192*1024];     // attention out (fp16)
__device__ float  sc_g  [8192*4096];
__device__ float  sc_u  [8192*4096];
__device__ __half sc_gh [8192*4096];     // swiglu out (fp16)
__device__ float  sc_cos[2048*32];
__device__ float  sc_sin[2048*32];
__device__ __half sc_w  [28311552];      // all weights fp16, packed

// weight offsets (elements)
#define OFF_WQ  0
#define OFF_WK  1048576
#define OFF_WV  1572864
#define OFF_WO  2097152
#define OFF_WG  3145728
#define OFF_WU  7340032
#define OFF_WD  11534336
#define OFF_EG  15728640
#define OFF_EU  19922944
#define OFF_ED  24117248

// ---------------- fp32 -> fp16 convert ----------------
__global__ __launch_bounds__(256)
void f2h_kernel(const float* __restrict__ s, __half* __restrict__ d)
{
    size_t i = ((size_t)blockIdx.x * 256 + threadIdx.x) * 8;
    float4 a = *(const float4*)(s + i);
    float4 b = *(const float4*)(s + i + 4);
    __half2 h0 = __floats2half2_rn(a.x, a.y);
    __half2 h1 = __floats2half2_rn(a.z, a.w);
    __half2 h2 = __floats2half2_rn(b.x, b.y);
    __half2 h3 = __floats2half2_rn(b.z, b.w);
    uint4 o;
    o.x = *(uint32_t*)&h0; o.y = *(uint32_t*)&h1;
    o.z = *(uint32_t*)&h2; o.w = *(uint32_t*)&h3;
    *(uint4*)(d + i) = o;
}

// ---------------- rmsnorm (fp32 in -> fp16 out) ----------------
__global__ __launch_bounds__(256)
void rmsnorm_kernel(const float* __restrict__ x, const float* __restrict__ w,
                    __half* __restrict__ out)
{
    int t = blockIdx.x;
    const float* xr = x + (size_t)t * 1024;
    __half* orow = out + (size_t)t * 1024;
    int tid = threadIdx.x;

    float4 v = *(const float4*)(xr + tid * 4);
    float s = v.x*v.x + v.y*v.y + v.z*v.z + v.w*v.w;
    #pragma unroll
    for (int o = 16; o; o >>= 1) s += __shfl_xor_sync(0xffffffffu, s, o);
    __shared__ float ws[8];
    if ((tid & 31) == 0) ws[tid >> 5] = s;
    __syncthreads();
    if (tid < 8) {
        float t2 = ws[tid];
        #pragma unroll
        for (int o = 4; o; o >>= 1) t2 += __shfl_xor_sync(0xffu, t2, o);
        if (tid == 0) ws[0] = t2;
    }
    __syncthreads();
    float rinv = rsqrtf(ws[0] * (1.0f / 1024.0f) + 1e-6f);
    float4 wv = *(const float4*)(w + tid * 4);
    __half2 r0 = __floats2half2_rn(v.x * rinv * wv.x, v.y * rinv * wv.y);
    __half2 r1 = __floats2half2_rn(v.z * rinv * wv.z, v.w * rinv * wv.w);
    uint2 o;
    o.x = *(uint32_t*)&r0; o.y = *(uint32_t*)&r1;
    *(uint2*)(orow + tid * 4) = o;
}

// ---------------- pipelined fp16 GEMM ----------------
// C[M,N](fp32) = A[M,K](fp16) @ B[K,N](fp16) (+bias/res/accum)
// Blocked-B: addr(k,n) = B + (n/nbs)*nstride + k*ldb + (n%nbs)
// 3-stage cp.async, KTILE=32, block 128x128, 8 warps of 32x64, 2 CTAs/SM.
#define GBK   32
#define GLDA  40                 // halves
#define GLDB  136
#define ASTG  (128 * GLDA)       // halves per A stage
#define BSTG  (GBK * GLDB)
#define GSMEM ((3 * (ASTG + BSTG)) * 2)

__device__ __forceinline__ void cp16(uint32_t saddr, const void* g)
{
    asm volatile("cp.async.cg.shared.global [%0], [%1], 16;\n" :: "r"(saddr), "l"(g));
}
#define CP_COMMIT() asm volatile("cp.async.commit_group;\n" ::)
#define CP_WAIT1()  asm volatile("cp.async.wait_group 1;\n" ::)

__global__ __launch_bounds__(256, 2)
void gemm_h(const __half* __restrict__ A, const __half* __restrict__ B,
            float* __restrict__ C, int M, int N, int K,
            int ldb, int nbs, long long nstride,
            const float* __restrict__ bias, const float* __restrict__ res,
            int accum)
{
    extern __shared__ __half sm[];
    __half* As = sm;
    __half* Bs = sm + 3 * ASTG;
    uint32_t smemBase = (uint32_t)__cvta_generic_to_shared(sm);

    int bm = blockIdx.y * 128, bn = blockIdx.x * 128;
    int tid = threadIdx.x, wid = tid >> 5, lane = tid & 31;
    int wm = (wid >> 1) * 32, wn = (wid & 1) * 64;

    wmma::fragment<wmma::accumulator, 16, 16, 16, float> acc[2][4];
    #pragma unroll
    for (int i = 0; i < 2; i++)
        #pragma unroll
        for (int j = 0; j < 4; j++) wmma::fill_fragment(acc[i][j], 0.0f);

    int nk = K / GBK;

    auto prefetch = [&](int s, int k0) {
        uint32_t as = smemBase + (uint32_t)(s * ASTG) * 2;
        uint32_t bs = smemBase + (uint32_t)(3 * ASTG + s * BSTG) * 2;
        // A: 128 rows x 4 chunks of 8 halves = 512 chunks
        #pragma unroll
        for (int it = 0; it < 2; it++) {
            int j = tid + it * 256;
            int r = j >> 2, c8 = j & 3;
            cp16(as + (uint32_t)(r * GLDA + c8 * 8) * 2,
                 A + (size_t)(bm + r) * K + k0 + c8 * 8);
        }
        // B: 32 rows x 16 chunks of 8 halves = 512 chunks
        #pragma unroll
        for (int it = 0; it < 2; it++) {
            int j = tid + it * 256;
            int r = j >> 4, c8 = j & 15;
            int n = bn + c8 * 8;
            const __half* bp = B + (size_t)(n / nbs) * nstride
                                 + (size_t)(k0 + r) * ldb + (n % nbs);
            cp16(bs + (uint32_t)(r * GLDB + c8 * 8) * 2, bp);
        }
    };

    prefetch(0, 0);     CP_COMMIT();
    prefetch(1, GBK);   CP_COMMIT();

    for (int i = 0; i < nk; i++) {
        CP_WAIT1();
        __syncthreads();

        int s = i % 3;
        const __half* as = As + s * ASTG;
        const __half* bs = Bs + s * BSTG;
        #pragma unroll
        for (int kk = 0; kk < GBK; kk += 16) {
            wmma::fragment<wmma::matrix_a, 16, 16, 16, __half, wmma::row_major> af[2];
            wmma::fragment<wmma::matrix_b, 16, 16, 16, __half, wmma::row_major> bf[4];
            #pragma unroll
            for (int ii = 0; ii < 2; ii++)
                wmma::load_matrix_sync(af[ii], as + (wm + ii * 16) * GLDA + kk, GLDA);
            #pragma unroll
            for (int jj = 0; jj < 4; jj++)
                wmma::load_matrix_sync(bf[jj], bs + kk * GLDB + wn + jj * 16, GLDB);
            #pragma unroll
            for (int ii = 0; ii < 2; ii++)
                #pragma unroll
                for (int jj = 0; jj < 4; jj++)
                    wmma::mma_sync(acc[ii][jj], af[ii], bf[jj], acc[ii][jj]);
        }

        int next = i + 2;
        if (next < nk) prefetch(next % 3, next * GBK);
        CP_COMMIT();
        __syncthreads();
    }

    // epilogue: stage each 16x16 frag through smem (as fp32)
    float* buf = (float*)sm + wid * 256;
    #pragma unroll
    for (int i = 0; i < 2; i++)
        for (int j = 0; j < 4; j++) {
            wmma::store_matrix_sync(buf, acc[i][j], 16, wmma::mem_row_major);
            __syncwarp();
            int r0 = bm + wm + i * 16, c0 = bn + wn + j * 16;
            #pragma unroll
            for (int t2 = 0; t2 < 8; t2++) {
                int e = lane * 8 + t2;
                int er = e >> 4, ec = e & 15;
                float vv = buf[e];
                if (bias) vv += bias[c0 + ec];
                size_t ci = (size_t)(r0 + er) * N + (c0 + ec);
                if (res)   vv += res[ci];
                if (accum) vv += C[ci];
                C[ci] = vv;
            }
            __syncwarp();
        }
}

// ---------------- RoPE ----------------
__global__ void rope_table(float* __restrict__ ct, float* __restrict__ st)
{
    int i = blockIdx.x * 256 + threadIdx.x;
    int p = i >> 5, j = i & 31;
    float inv = powf(10000.0f, -(float)j * (1.0f / 32.0f));
    float ang = (float)p * inv;
    float s, c;
    sincosf(ang, &s, &c);
    ct[i] = c; st[i] = s;
}

__global__ void rope_apply(float* __restrict__ v, int nh,
                           const float* __restrict__ ct, const float* __restrict__ st)
{
    int i = blockIdx.x * 256 + threadIdx.x;
    int tot = T_TOK * nh * 32;
    if (i >= tot) return;
    int j = i & 31;
    int h = (i >> 5) % nh;
    int t = i / (nh * 32);
    int p = t & (NPOS - 1);
    float c = ct[p * 32 + j], s = st[p * 32 + j];
    size_t base = (size_t)t * nh * 64 + h * 64;
    float v1 = v[base + j], v2 = v[base + 32 + j];
    v[base + j]      = v1 * c - v2 * s;
    v[base + 32 + j] = v2 * c + v1 * s;
}

// ---------------- flash attention (causal, GQA 2:1, HD=64, TF32) ----------------
#define FLD 72
__global__ __launch_bounds__(256)
void flash_attn(const float* __restrict__ q, const float* __restrict__ k,
                const float* __restrict__ v, __half* __restrict__ o)
{
    extern __shared__ float smf[];
    float* Qs = smf;
    float* Ks = Qs + 64 * FLD;
    float* Vs = Ks + 64 * FLD;
    float* Ss = Vs + 64 * FLD;
    float* Os = Ss + 64 * FLD;
    float* mrow = Os + 64 * FLD;
    float* lrow = mrow + 64;
    float* crow = lrow + 64;

    int qt = blockIdx.x, h = blockIdx.y, b = blockIdx.z;
    int tid = threadIdx.x, wid = tid >> 5;
    int kvh = h >> 1;

    const float* qb = q + ((size_t)(b * NPOS + qt * 64)) * 1024 + h * 64;
    for (int i = tid; i < 1024; i += 256) {
        int r = i >> 4, c4 = i & 15;
        float4 val = *(const float4*)(qb + (size_t)r * 1024 + c4 * 4);
        val.x *= 0.125f; val.y *= 0.125f; val.z *= 0.125f; val.w *= 0.125f;
        *(float4*)(Qs + r * FLD + c4 * 4) = val;
    }
    for (int i = tid; i < 4096; i += 256) {
        int r = i >> 6, c = i & 63;
        Os[r * FLD + c] = 0.0f;
    }
    if (tid < 64) { mrow[tid] = -1e30f; lrow[tid] = 0.0f; }
    __syncthreads();

    int wm = (wid >> 1) * 16, wn = (wid & 1) * 32;

    for (int kt = 0; kt <= qt; kt++) {
        const float* kb = k + ((size_t)(b * NPOS + kt * 64)) * 512 + kvh * 64;
        const float* vb = v + ((size_t)(b * NPOS + kt * 64)) * 512 + kvh * 64;
        for (int i = tid; i < 1024; i += 256) {
            int r = i >> 4, c4 = i & 15;
            *(float4*)(Ks + r * FLD + c4 * 4) = *(const float4*)(kb + (size_t)r * 512 + c4 * 4);
            *(float4*)(Vs + r * FLD + c4 * 4) = *(const float4*)(vb + (size_t)r * 512 + c4 * 4);
        }
        __syncthreads();

        {
            wmma::fragment<wmma::accumulator, 16, 16, 8, float> sacc[2];
            wmma::fill_fragment(sacc[0], 0.0f);
            wmma::fill_fragment(sacc[1], 0.0f);
            for (int d = 0; d < 64; d += 8) {
                wmma::fragment<wmma::matrix_a, 16, 16, 8, wmma::precision::tf32, wmma::row_major> af;
                wmma::load_matrix_sync(af, Qs + wm * FLD + d, FLD);
                #pragma unroll
                for (int e = 0; e < af.num_elements; e++) af.x[e] = wmma::__float_to_tf32(af.x[e]);
                #pragma unroll
                for (int j = 0; j < 2; j++) {
                    wmma::fragment<wmma::matrix_b, 16, 16, 8, wmma::precision::tf32, wmma::col_major> bf;
                    wmma::load_matrix_sync(bf, Ks + (wn + j * 16) * FLD + d, FLD);
                    #pragma unroll
                    for (int e = 0; e < bf.num_elements; e++) bf.x[e] = wmma::__float_to_tf32(bf.x[e]);
                    wmma::mma_sync(sacc[j], af, bf, sacc[j]);
                }
            }
            wmma::store_matrix_sync(Ss + wm * FLD + wn,      sacc[0], FLD, wmma::mem_row_major);
            wmma::store_matrix_sync(Ss + wm * FLD + wn + 16, sacc[1], FLD, wmma::mem_row_major);
        }
        __syncthreads();

        {
            int r = tid >> 2, pp = tid & 3;
            int qg = qt * 64 + r;
            float vals[16]; float mx = -1e30f;
            #pragma unroll
            for (int c = 0; c < 16; c++) {
                int col = pp * 16 + c;
                float sv = Ss[r * FLD + col];
                if (kt * 64 + col > qg) sv = -1e30f;
                vals[c] = sv; mx = fmaxf(mx, sv);
            }
            mx = fmaxf(mx, __shfl_xor_sync(0xffffffffu, mx, 1));
            mx = fmaxf(mx, __shfl_xor_sync(0xffffffffu, mx, 2));
            float mold = mrow[r];
            float mnew = fmaxf(mold, mx);
            float sum = 0.0f;
            #pragma unroll
            for (int c = 0; c < 16; c++) {
                float e = __expf(vals[c] - mnew);
                Ss[r * FLD + pp * 16 + c] = e;
                sum += e;
            }
            sum += __shfl_xor_sync(0xffffffffu, sum, 1);
            sum += __shfl_xor_sync(0xffffffffu, sum, 2);
            if (pp == 0) {
                float cc = __expf(mold - mnew);
                lrow[r] = lrow[r] * cc + sum;
                mrow[r] = mnew;
                crow[r] = cc;
            }
        }
        __syncthreads();

        {
            wmma::fragment<wmma::accumulator, 16, 16, 8, float> pv[2];
            wmma::fill_fragment(pv[0], 0.0f);
            wmma::fill_fragment(pv[1], 0.0f);
            for (int kk = 0; kk < 64; kk += 8) {
                wmma::fragment<wmma::matrix_a, 16, 16, 8, wmma::precision::tf32, wmma::row_major> af;
                wmma::load_matrix_sync(af, Ss + wm * FLD + kk, FLD);
                #pragma unroll
                for (int e = 0; e < af.num_elements; e++) af.x[e] = wmma::__float_to_tf32(af.x[e]);
                #pragma unroll
                for (int j = 0; j < 2; j++) {
                    wmma::fragment<wmma::matrix_b, 16, 16, 8, wmma::precision::tf32, wmma::row_major> bf;
                    wmma::load_matrix_sync(bf, Vs + kk * FLD + wn + j * 16, FLD);
                    #pragma unroll
                    for (int e = 0; e < bf.num_elements; e++) bf.x[e] = wmma::__float_to_tf32(bf.x[e]);
                    wmma::mma_sync(pv[j], af, bf, pv[j]);
                }
            }
            wmma::store_matrix_sync(Ks + wm * FLD + wn,      pv[0], FLD, wmma::mem_row_major);
            wmma::store_matrix_sync(Ks + wm * FLD + wn + 16, pv[1], FLD, wmma::mem_row_major);
        }
        __syncthreads();

        for (int i = tid; i < 4096; i += 256) {
            int r = i >> 6, c = i & 63;
            Os[r * FLD + c] = Os[r * FLD + c] * crow[r] + Ks[r * FLD + c];
        }
        __syncthreads();
    }

    __half* ob = o + ((size_t)(b * NPOS + qt * 64)) * 1024 + h * 64;
    for (int i = tid; i < 4096; i += 256) {
        int r = i >> 6, c = i & 63;
        ob[(size_t)r * 1024 + c] = __float2half(Os[r * FLD + c] / lrow[r]);
    }
}

// ---------------- SwiGLU -> fp16 (+optional expert-mask fold) ----------------
__global__ __launch_bounds__(256)
void swiglu_kernel(const float* __restrict__ g, const float* __restrict__ u,
                   __half* __restrict__ out, const float* __restrict__ mask)
{
    size_t i = (size_t)blockIdx.x * 256 + threadIdx.x;
    float gv = g[i], uv = u[i];
    float a = gv / (1.0f + __expf(-gv)) * uv;
    if (mask) {
        size_t t = i >> 12;
        int e = (int)((i >> 8) & 15);
        a *= mask[t * 16 + e];
    }
    out[i] = __float2half(a);
}

// ---------------- launch ----------------
extern "C" void kernel_launch(void* const* d_in, const int* in_sizes, int n_in,
                              void* d_out, int out_size)
{
    const float* x       = (const float*)d_in[0];
    const float* emask   = (const float*)d_in[1];
    const float* ln1     = (const float*)d_in[2];
    const float* wq      = (const float*)d_in[3];
    const float* bq      = (const float*)d_in[4];
    const float* wk      = (const float*)d_in[5];
    const float* bk      = (const float*)d_in[6];
    const float* wv      = (const float*)d_in[7];
    const float* bv      = (const float*)d_in[8];
    const float* wo      = (const float*)d_in[9];
    const float* ln2     = (const float*)d_in[10];
    const float* w_gate  = (const float*)d_in[11];
    const float* w_up    = (const float*)d_in[12];
    const float* w_down  = (const float*)d_in[13];
    const float* we_gate = (const float*)d_in[14];
    const float* we_up   = (const float*)d_in[15];
    const float* we_down = (const float*)d_in[16];
    float* out = (float*)d_out;

    __half *hh, *aoh, *gh, *w;
    float *qb, *kb, *vb, *g, *u, *ct, *st;
    cudaGetSymbolAddress((void**)&hh,  sc_hh);
    cudaGetSymbolAddress((void**)&qb,  sc_q);
    cudaGetSymbolAddress((void**)&kb,  sc_k);
    cudaGetSymbolAddress((void**)&vb,  sc_v);
    cudaGetSymbolAddress((void**)&aoh, sc_aoh);
    cudaGetSymbolAddress((void**)&g,   sc_g);
    cudaGetSymbolAddress((void**)&u,   sc_u);
    cudaGetSymbolAddress((void**)&gh,  sc_gh);
    cudaGetSymbolAddress((void**)&ct,  sc_cos);
    cudaGetSymbolAddress((void**)&st,  sc_sin);
    cudaGetSymbolAddress((void**)&w,   sc_w);

    const int FLASH_SMEM = (5 * 64 * FLD + 3 * 64) * 4;
    cudaFuncSetAttribute(flash_attn, cudaFuncAttributeMaxDynamicSharedMemorySize, FLASH_SMEM);
    cudaFuncSetAttribute(gemm_h, cudaFuncAttributeMaxDynamicSharedMemorySize, GSMEM);

    const int M = T_TOK;
    const int NB = 1 << 28;
    dim3 thr(256);

    // weight conversions (fp32 -> fp16)
    f2h_kernel<<< 512, 256>>>(wq,      w + OFF_WQ);
    f2h_kernel<<< 256, 256>>>(wk,      w + OFF_WK);
    f2h_kernel<<< 256, 256>>>(wv,      w + OFF_WV);
    f2h_kernel<<< 512, 256>>>(wo,      w + OFF_WO);
    f2h_kernel<<<2048, 256>>>(w_gate,  w + OFF_WG);
    f2h_kernel<<<2048, 256>>>(w_up,    w + OFF_WU);
    f2h_kernel<<<2048, 256>>>(w_down,  w + OFF_WD);
    f2h_kernel<<<2048, 256>>>(we_gate, w + OFF_EG);
    f2h_kernel<<<2048, 256>>>(we_up,   w + OFF_EU);
    f2h_kernel<<<2048, 256>>>(we_down, w + OFF_ED);

    rmsnorm_kernel<<<M, 256>>>(x, ln1, hh);

    gemm_h<<<dim3(8, 64), thr, GSMEM>>>(hh, w + OFF_WQ, qb, M, 1024, 1024, 1024, NB, 0, bq, nullptr, 0);
    gemm_h<<<dim3(4, 64), thr, GSMEM>>>(hh, w + OFF_WK, kb, M,  512, 1024,  512, NB, 0, bk, nullptr, 0);
    gemm_h<<<dim3(4, 64), thr, GSMEM>>>(hh, w + OFF_WV, vb, M,  512, 1024,  512, NB, 0, bv, nullptr, 0);

    rope_table<<<256, 256>>>(ct, st);
    rope_apply<<<16384, 256>>>(qb, 16, ct, st);
    rope_apply<<< 8192, 256>>>(kb,  8, ct, st);

    flash_attn<<<dim3(32, 16, 4), 256, FLASH_SMEM>>>(qb, kb, vb, aoh);

    gemm_h<<<dim3(8, 64), thr, GSMEM>>>(aoh, w + OFF_WO, out, M, 1024, 1024, 1024, NB, 0, nullptr, x, 0);

    rmsnorm_kernel<<<M, 256>>>(out, ln2, hh);

    gemm_h<<<dim3(32, 64), thr, GSMEM>>>(hh, w + OFF_WG, g, M, 4096, 1024, 4096, NB, 0, nullptr, nullptr, 0);
    gemm_h<<<dim3(32, 64), thr, GSMEM>>>(hh, w + OFF_WU, u, M, 4096, 1024, 4096, NB, 0, nullptr, nullptr, 0);
    swiglu_kernel<<<131072, 256>>>(g, u, gh, nullptr);
    gemm_h<<<dim3(8, 64), thr, GSMEM>>>(gh, w + OFF_WD, out, M, 1024, 4096, 1024, NB, 0, nullptr, nullptr, 1);

    gemm_h<<<dim3(32, 64), thr, GSMEM>>>(hh, w + OFF_EG, g, M, 4096, 1024, 256, 256, 1024LL * 256, nullptr, nullptr, 0);
    gemm_h<<<dim3(32, 64), thr, GSMEM>>>(hh, w + OFF_EU, u, M, 4096, 1024, 256, 256, 1024LL * 256, nullptr, nullptr, 0);
    swiglu_kernel<<<131072, 256>>>(g, u, gh, emask);
    gemm_h<<<dim3(8, 64), thr, GSMEM>>>(gh, w + OFF_ED, out, M, 1024, 4096, 1024, NB, 0, nullptr, nullptr, 1);
}

// round 4
// speedup vs baseline: 4.6229x; 1.3148x over previous
#include <cuda_runtime.h>
#include <cuda_fp16.h>
#include <mma.h>
#include <cstdint>

using namespace nvcuda;

// Shapes: B=4, P=2048 -> T=8192 tokens, D=1024, H=16, KV=8, HD=64, F=4096, E=16, FE=256
#define T_TOK 8192
#define NPOS  2048

// ---------------- scratch (device globals) ----------------
__device__ __half sc_hh  [8192*1024];        // rmsnorm out (fp16)
__device__ __half sc_qkv [8192*2048];        // q|k|v packed fp16
__device__ __half sc_aoh [8192*1024];        // attention out fp16
__device__ __half sc_gu  [(size_t)8192*16384]; // gate|up|egate|eup fp16
__device__ __half sc_act [(size_t)8192*8192];  // swiglu activations fp16
__device__ float  sc_cos [2048*32];
__device__ float  sc_sin [2048*32];
__device__ float  sc_bias[2048];
__device__ __half sc_w   [28311552];         // packed fp16 weights

// packed weight offsets (elements)
#define OFF_QKV 0                 // [1024, 2048]
#define OFF_WO  2097152           // [1024, 1024]
#define OFF_GU  3145728           // [1024, 16384]
#define OFF_DN  19922944          // [8192, 1024]

// ---------------- weight packing ----------------
__global__ __launch_bounds__(256)
void f2h_kernel(const float* __restrict__ s, __half* __restrict__ d)
{
    size_t i = ((size_t)blockIdx.x * 256 + threadIdx.x) * 8;
    float4 a = *(const float4*)(s + i);
    float4 b = *(const float4*)(s + i + 4);
    __half2 h0 = __floats2half2_rn(a.x, a.y);
    __half2 h1 = __floats2half2_rn(a.z, a.w);
    __half2 h2 = __floats2half2_rn(b.x, b.y);
    __half2 h3 = __floats2half2_rn(b.z, b.w);
    uint4 o;
    o.x = *(uint32_t*)&h0; o.y = *(uint32_t*)&h1;
    o.z = *(uint32_t*)&h2; o.w = *(uint32_t*)&h3;
    *(uint4*)(d + i) = o;
}

__global__ __launch_bounds__(256)
void pack_qkv(const float* __restrict__ wq, const float* __restrict__ wk,
              const float* __restrict__ wv, __half* __restrict__ d)
{
    int i = blockIdx.x * 256 + threadIdx.x;     // 1024*2048
    int r = i >> 11, c = i & 2047;
    float v;
    if (c < 1024)      v = wq[r * 1024 + c];
    else if (c < 1536) v = wk[r * 512 + (c - 1024)];
    else               v = wv[r * 512 + (c - 1536)];
    d[i] = __float2half(v);
}

__global__ __launch_bounds__(256)
void pack_bias(const float* __restrict__ bq, const float* __restrict__ bk,
               const float* __restrict__ bv, float* __restrict__ d)
{
    int c = blockIdx.x * 256 + threadIdx.x;     // 2048
    float v;
    if (c < 1024)      v = bq[c];
    else if (c < 1536) v = bk[c - 1024];
    else               v = bv[c - 1536];
    d[c] = v;
}

__global__ __launch_bounds__(256)
void pack_gu(const float* __restrict__ wg, const float* __restrict__ wu,
             const float* __restrict__ eg, const float* __restrict__ eu,
             __half* __restrict__ d)
{
    size_t i = (size_t)blockIdx.x * 256 + threadIdx.x;  // 1024*16384
    int r = (int)(i >> 14), c = (int)(i & 16383);
    float v;
    if (c < 4096)       v = wg[(size_t)r * 4096 + c];
    else if (c < 8192)  v = wu[(size_t)r * 4096 + (c - 4096)];
    else if (c < 12288) {
        int ce = c - 8192, e = ce >> 8, f = ce & 255;
        v = eg[((size_t)e * 1024 + r) * 256 + f];
    } else {
        int ce = c - 12288, e = ce >> 8, f = ce & 255;
        v = eu[((size_t)e * 1024 + r) * 256 + f];
    }
    d[i] = __float2half(v);
}

__global__ __launch_bounds__(256)
void pack_down(const float* __restrict__ wd, const float* __restrict__ ed,
               __half* __restrict__ d)
{
    size_t i = (size_t)blockIdx.x * 256 + threadIdx.x;  // 8192*1024
    int r = (int)(i >> 10), c = (int)(i & 1023);
    float v;
    if (r < 4096) v = wd[(size_t)r * 1024 + c];
    else {
        int r2 = r - 4096, e = r2 >> 8, f = r2 & 255;
        v = ed[((size_t)e * 256 + f) * 1024 + c];
    }
    d[i] = __float2half(v);
}

// ---------------- rmsnorm (fp32 in -> fp16 out) ----------------
__global__ __launch_bounds__(256)
void rmsnorm_kernel(const float* __restrict__ x, const float* __restrict__ w,
                    __half* __restrict__ out)
{
    int t = blockIdx.x;
    const float* xr = x + (size_t)t * 1024;
    __half* orow = out + (size_t)t * 1024;
    int tid = threadIdx.x;

    float4 v = *(const float4*)(xr + tid * 4);
    float s = v.x*v.x + v.y*v.y + v.z*v.z + v.w*v.w;
    #pragma unroll
    for (int o = 16; o; o >>= 1) s += __shfl_xor_sync(0xffffffffu, s, o);
    __shared__ float ws[8];
    if ((tid & 31) == 0) ws[tid >> 5] = s;
    __syncthreads();
    if (tid < 8) {
        float t2 = ws[tid];
        #pragma unroll
        for (int o = 4; o; o >>= 1) t2 += __shfl_xor_sync(0xffu, t2, o);
        if (tid == 0) ws[0] = t2;
    }
    __syncthreads();
    float rinv = rsqrtf(ws[0] * (1.0f / 1024.0f) + 1e-6f);
    float4 wv = *(const float4*)(w + tid * 4);
    __half2 r0 = __floats2half2_rn(v.x * rinv * wv.x, v.y * rinv * wv.y);
    __half2 r1 = __floats2half2_rn(v.z * rinv * wv.z, v.w * rinv * wv.w);
    uint2 o;
    o.x = *(uint32_t*)&r0; o.y = *(uint32_t*)&r1;
    *(uint2*)(orow + tid * 4) = o;
}

// ---------------- pipelined fp16 GEMM ----------------
// C = A[M,K] @ B[K,N] (+bias/res/accum). fp32 out (C) or fp16 out (Ch).
#define GBK   32
#define GLDA  40
#define GLDB  136
#define ASTG  (128 * GLDA)
#define BSTG  (GBK * GLDB)
#define GSMEM ((3 * (ASTG + BSTG)) * 2)

__device__ __forceinline__ void cp16(uint32_t saddr, const void* g)
{
    asm volatile("cp.async.cg.shared.global [%0], [%1], 16;\n" :: "r"(saddr), "l"(g));
}
#define CP_COMMIT() asm volatile("cp.async.commit_group;\n" ::)
#define CP_WAIT1()  asm volatile("cp.async.wait_group 1;\n" ::)
#define CP_WAIT0()  asm volatile("cp.async.wait_group 0;\n" ::)

__global__ __launch_bounds__(256, 2)
void gemm_h(const __half* __restrict__ A, const __half* __restrict__ B,
            float* __restrict__ C, __half* __restrict__ Ch,
            int M, int N, int K,
            const float* __restrict__ bias, const float* __restrict__ res,
            int accum)
{
    extern __shared__ __half sm[];
    __half* As = sm;
    __half* Bs = sm + 3 * ASTG;
    uint32_t smemBase = (uint32_t)__cvta_generic_to_shared(sm);

    int bm = blockIdx.y * 128, bn = blockIdx.x * 128;
    int tid = threadIdx.x, wid = tid >> 5, lane = tid & 31;
    int wm = (wid >> 1) * 32, wn = (wid & 1) * 64;

    wmma::fragment<wmma::accumulator, 16, 16, 16, float> acc[2][4];
    #pragma unroll
    for (int i = 0; i < 2; i++)
        #pragma unroll
        for (int j = 0; j < 4; j++) wmma::fill_fragment(acc[i][j], 0.0f);

    int nk = K / GBK;

    auto prefetch = [&](int s, int k0) {
        uint32_t as = smemBase + (uint32_t)(s * ASTG) * 2;
        uint32_t bs = smemBase + (uint32_t)(3 * ASTG + s * BSTG) * 2;
        #pragma unroll
        for (int it = 0; it < 2; it++) {
            int j = tid + it * 256;
            int r = j >> 2, c8 = j & 3;
            cp16(as + (uint32_t)(r * GLDA + c8 * 8) * 2,
                 A + (size_t)(bm + r) * K + k0 + c8 * 8);
        }
        #pragma unroll
        for (int it = 0; it < 2; it++) {
            int j = tid + it * 256;
            int r = j >> 4, c8 = j & 15;
            cp16(bs + (uint32_t)(r * GLDB + c8 * 8) * 2,
                 B + (size_t)(k0 + r) * N + bn + c8 * 8);
        }
    };

    prefetch(0, 0);     CP_COMMIT();
    prefetch(1, GBK);   CP_COMMIT();

    for (int i = 0; i < nk; i++) {
        CP_WAIT1();
        __syncthreads();

        int s = i % 3;
        const __half* as = As + s * ASTG;
        const __half* bs = Bs + s * BSTG;
        #pragma unroll
        for (int kk = 0; kk < GBK; kk += 16) {
            wmma::fragment<wmma::matrix_a, 16, 16, 16, __half, wmma::row_major> af[2];
            wmma::fragment<wmma::matrix_b, 16, 16, 16, __half, wmma::row_major> bf[4];
            #pragma unroll
            for (int ii = 0; ii < 2; ii++)
                wmma::load_matrix_sync(af[ii], as + (wm + ii * 16) * GLDA + kk, GLDA);
            #pragma unroll
            for (int jj = 0; jj < 4; jj++)
                wmma::load_matrix_sync(bf[jj], bs + kk * GLDB + wn + jj * 16, GLDB);
            #pragma unroll
            for (int ii = 0; ii < 2; ii++)
                #pragma unroll
                for (int jj = 0; jj < 4; jj++)
                    wmma::mma_sync(acc[ii][jj], af[ii], bf[jj], acc[ii][jj]);
        }

        int next = i + 2;
        if (next < nk) prefetch(next % 3, next * GBK);
        CP_COMMIT();
    }

    __syncthreads();

    float* buf = (float*)sm + wid * 256;
    #pragma unroll
    for (int i = 0; i < 2; i++)
        for (int j = 0; j < 4; j++) {
            wmma::store_matrix_sync(buf, acc[i][j], 16, wmma::mem_row_major);
            __syncwarp();
            int r0 = bm + wm + i * 16, c0 = bn + wn + j * 16;
            #pragma unroll
            for (int t2 = 0; t2 < 8; t2++) {
                int e = lane * 8 + t2;
                int er = e >> 4, ec = e & 15;
                float vv = buf[e];
                if (bias) vv += bias[c0 + ec];
                size_t ci = (size_t)(r0 + er) * N + (c0 + ec);
                if (res)   vv += res[ci];
                if (accum) vv += C[ci];
                if (Ch) Ch[ci] = __float2half(vv);
                else    C[ci]  = vv;
            }
            __syncwarp();
        }
}

// ---------------- RoPE ----------------
__global__ void rope_table(float* __restrict__ ct, float* __restrict__ st)
{
    int i = blockIdx.x * 256 + threadIdx.x;
    int p = i >> 5, j = i & 31;
    float inv = powf(10000.0f, -(float)j * (1.0f / 32.0f));
    float ang = (float)p * inv;
    float s, c;
    sincosf(ang, &s, &c);
    ct[i] = c; st[i] = s;
}

// qkv layout: token-major stride 2048; q at col 0, k at col 1024
__global__ void rope_apply(__half* __restrict__ qkv, int nh, int coff,
                           const float* __restrict__ ct, const float* __restrict__ st)
{
    int i = blockIdx.x * 256 + threadIdx.x;
    int tot = T_TOK * nh * 32;
    if (i >= tot) return;
    int j = i & 31;
    int h = (i >> 5) % nh;
    int t = i / (nh * 32);
    int p = t & (NPOS - 1);
    float c = ct[p * 32 + j], s = st[p * 32 + j];
    size_t base = (size_t)t * 2048 + coff + h * 64;
    float v1 = __half2float(qkv[base + j]);
    float v2 = __half2float(qkv[base + 32 + j]);
    qkv[base + j]      = __float2half(v1 * c - v2 * s);
    qkv[base + 32 + j] = __float2half(v2 * c + v1 * s);
}

// ---------------- fp16 flash attention (causal, GQA 2:1, HD=64) ----------------
#define FLD 72
#define FT  4608   // 64*72 halves per tile
__global__ __launch_bounds__(256)
void flash16(const __half* __restrict__ qkv, __half* __restrict__ o)
{
    extern __shared__ __half smh[];
    __half* Qs = smh;                // 64x72
    __half* Ks = Qs + FT;            // 2 bufs
    __half* Vs = Ks + 2 * FT;        // 2 bufs
    __half* Ps = Vs + 2 * FT;        // 64x72
    float*  Ss = (float*)(Ps + FT);  // 64x72 fp32
    float*  Os = Ss + FT;
    float*  mrow = Os + FT;
    float*  lrow = mrow + 64;
    float*  crow = lrow + 64;
    uint32_t smemBase = (uint32_t)__cvta_generic_to_shared(smh);

    int qt = blockIdx.x, h = blockIdx.y, b = blockIdx.z;
    int tid = threadIdx.x, wid = tid >> 5;
    int kvh = h >> 1;

    // load + scale Q (1/8)
    const __half* qb = qkv + ((size_t)(b * NPOS + qt * 64)) * 2048 + h * 64;
    const __half2 sc8 = __floats2half2_rn(0.125f, 0.125f);
    for (int it = 0; it < 2; it++) {
        int j = tid + it * 256;
        int r = j >> 3, c8 = j & 7;
        uint4 raw = *(const uint4*)(qb + (size_t)r * 2048 + c8 * 8);
        __half2* hp = (__half2*)&raw;
        #pragma unroll
        for (int q2 = 0; q2 < 4; q2++) hp[q2] = __hmul2(hp[q2], sc8);
        *(uint4*)(Qs + r * FLD + c8 * 8) = raw;
    }
    for (int i = tid; i < 4096; i += 256) {
        int r = i >> 6, c = i & 63;
        Os[r * FLD + c] = 0.0f;
    }
    if (tid < 64) { mrow[tid] = -1e30f; lrow[tid] = 0.0f; }

    auto pf = [&](int kt, int bi) {
        const __half* kb = qkv + ((size_t)(b * NPOS + kt * 64)) * 2048 + 1024 + kvh * 64;
        uint32_t ks = smemBase + (uint32_t)(FT + bi * FT) * 2;
        uint32_t vs = smemBase + (uint32_t)(3 * FT + bi * FT) * 2;
        #pragma unroll
        for (int it = 0; it < 2; it++) {
            int j = tid + it * 256;
            int r = j >> 3, c8 = j & 7;
            cp16(ks + (uint32_t)(r * FLD + c8 * 8) * 2, kb + (size_t)r * 2048 + c8 * 8);
            cp16(vs + (uint32_t)(r * FLD + c8 * 8) * 2, kb + (size_t)r * 2048 + 512 + c8 * 8);
        }
    };

    pf(0, 0);
    CP_COMMIT();
    __syncthreads();

    int wm = (wid >> 1) * 16, wn = (wid & 1) * 32;

    for (int kt = 0; kt <= qt; kt++) {
        int bi = kt & 1;
        CP_WAIT0();
        __syncthreads();
        if (kt < qt) pf(kt + 1, bi ^ 1);
        CP_COMMIT();

        const __half* kcur = Ks + bi * FT;
        const __half* vcur = Vs + bi * FT;

        { // S = Qs @ K^T
            wmma::fragment<wmma::accumulator, 16, 16, 16, float> sa[2];
            wmma::fill_fragment(sa[0], 0.0f);
            wmma::fill_fragment(sa[1], 0.0f);
            #pragma unroll
            for (int d = 0; d < 64; d += 16) {
                wmma::fragment<wmma::matrix_a, 16, 16, 16, __half, wmma::row_major> af;
                wmma::load_matrix_sync(af, Qs + wm * FLD + d, FLD);
                #pragma unroll
                for (int jj = 0; jj < 2; jj++) {
                    wmma::fragment<wmma::matrix_b, 16, 16, 16, __half, wmma::col_major> bf;
                    wmma::load_matrix_sync(bf, kcur + (wn + jj * 16) * FLD + d, FLD);
                    wmma::mma_sync(sa[jj], af, bf, sa[jj]);
                }
            }
            wmma::store_matrix_sync(Ss + wm * FLD + wn,      sa[0], FLD, wmma::mem_row_major);
            wmma::store_matrix_sync(Ss + wm * FLD + wn + 16, sa[1], FLD, wmma::mem_row_major);
        }
        __syncthreads();

        { // online softmax, P -> fp16
            int r = tid >> 2, pp = tid & 3;
            int qg = qt * 64 + r;
            float vals[16]; float mx = -1e30f;
            #pragma unroll
            for (int c = 0; c < 16; c++) {
                int col = pp * 16 + c;
                float sv = Ss[r * FLD + col];
                if (kt * 64 + col > qg) sv = -1e30f;
                vals[c] = sv; mx = fmaxf(mx, sv);
            }
            mx = fmaxf(mx, __shfl_xor_sync(0xffffffffu, mx, 1));
            mx = fmaxf(mx, __shfl_xor_sync(0xffffffffu, mx, 2));
            float mold = mrow[r];
            float mnew = fmaxf(mold, mx);
            float sum = 0.0f;
            #pragma unroll
            for (int c = 0; c < 16; c++) {
                float e = __expf(vals[c] - mnew);
                Ps[r * FLD + pp * 16 + c] = __float2half(e);
                sum += e;
            }
            sum += __shfl_xor_sync(0xffffffffu, sum, 1);
            sum += __shfl_xor_sync(0xffffffffu, sum, 2);
            if (pp == 0) {
                float cc = __expf(mold - mnew);
                lrow[r] = lrow[r] * cc + sum;
                mrow[r] = mnew;
                crow[r] = cc;
            }
        }
        __syncthreads();

        { // PV = Ps @ Vs  (staged via Ss fp32)
            wmma::fragment<wmma::accumulator, 16, 16, 16, float> pv[2];
            wmma::fill_fragment(pv[0], 0.0f);
            wmma::fill_fragment(pv[1], 0.0f);
            #pragma unroll
            for (int kk = 0; kk < 64; kk += 16) {
                wmma::fragment<wmma::matrix_a, 16, 16, 16, __half, wmma::row_major> af;
                wmma::load_matrix_sync(af, Ps + wm * FLD + kk, FLD);
                #pragma unroll
                for (int jj = 0; jj < 2; jj++) {
                    wmma::fragment<wmma::matrix_b, 16, 16, 16, __half, wmma::row_major> bf;
                    wmma::load_matrix_sync(bf, vcur + kk * FLD + wn + jj * 16, FLD);
                    wmma::mma_sync(pv[jj], af, bf, pv[jj]);
                }
            }
            wmma::store_matrix_sync(Ss + wm * FLD + wn,      pv[0], FLD, wmma::mem_row_major);
            wmma::store_matrix_sync(Ss + wm * FLD + wn + 16, pv[1], FLD, wmma::mem_row_major);
        }
        __syncthreads();

        for (int i = tid; i < 4096; i += 256) {
            int r = i >> 6, c = i & 63;
            Os[r * FLD + c] = Os[r * FLD + c] * crow[r] + Ss[r * FLD + c];
        }
        __syncthreads();
    }

    __half* ob = o + ((size_t)(b * NPOS + qt * 64)) * 1024 + h * 64;
    for (int i = tid; i < 4096; i += 256) {
        int r = i >> 6, c = i & 63;
        ob[(size_t)r * 1024 + c] = __float2half(Os[r * FLD + c] / lrow[r]);
    }
}

// ---------------- fused SwiGLU (dense + experts) ----------------
// gu: [T, 16384] = gate|up|egate|eup ; act: [T, 8192] = dense_act|expert_act
__global__ __launch_bounds__(256)
void swiglu2(const __half* __restrict__ gu, __half* __restrict__ act,
             const float* __restrict__ mask)
{
    size_t p = (size_t)blockIdx.x * 256 + threadIdx.x;  // T*4096 pairs
    size_t t = p >> 12;
    int jp = (int)(p & 4095);
    int c0 = jp * 2;
    const __half* row = gu + t * 16384;
    float2 gf, uf, m2 = make_float2(1.0f, 1.0f);
    if (c0 < 4096) {
        gf = __half22float2(*(const __half2*)(row + c0));
        uf = __half22float2(*(const __half2*)(row + 4096 + c0));
    } else {
        int je = c0 - 4096;
        gf = __half22float2(*(const __half2*)(row + 8192 + je));
        uf = __half22float2(*(const __half2*)(row + 12288 + je));
        float mk = mask[t * 16 + (je >> 8)];
        m2 = make_float2(mk, mk);
    }
    float a0 = gf.x / (1.0f + __expf(-gf.x)) * uf.x * m2.x;
    float a1 = gf.y / (1.0f + __expf(-gf.y)) * uf.y * m2.y;
    __half2 r = __floats2half2_rn(a0, a1);
    *(__half2*)(act + t * 8192 + c0) = r;
}

// ---------------- launch ----------------
extern "C" void kernel_launch(void* const* d_in, const int* in_sizes, int n_in,
                              void* d_out, int out_size)
{
    const float* x       = (const float*)d_in[0];
    const float* emask   = (const float*)d_in[1];
    const float* ln1     = (const float*)d_in[2];
    const float* wq      = (const float*)d_in[3];
    const float* bq      = (const float*)d_in[4];
    const float* wk      = (const float*)d_in[5];
    const float* bk      = (const float*)d_in[6];
    const float* wv      = (const float*)d_in[7];
    const float* bv      = (const float*)d_in[8];
    const float* wo      = (const float*)d_in[9];
    const float* ln2     = (const float*)d_in[10];
    const float* w_gate  = (const float*)d_in[11];
    const float* w_up    = (const float*)d_in[12];
    const float* w_down  = (const float*)d_in[13];
    const float* we_gate = (const float*)d_in[14];
    const float* we_up   = (const float*)d_in[15];
    const float* we_down = (const float*)d_in[16];
    float* out = (float*)d_out;

    __half *hh, *qkv, *aoh, *gu, *act, *w;
    float *ct, *st, *bias;
    cudaGetSymbolAddress((void**)&hh,   sc_hh);
    cudaGetSymbolAddress((void**)&qkv,  sc_qkv);
    cudaGetSymbolAddress((void**)&aoh,  sc_aoh);
    cudaGetSymbolAddress((void**)&gu,   sc_gu);
    cudaGetSymbolAddress((void**)&act,  sc_act);
    cudaGetSymbolAddress((void**)&w,    sc_w);
    cudaGetSymbolAddress((void**)&ct,   sc_cos);
    cudaGetSymbolAddress((void**)&st,   sc_sin);
    cudaGetSymbolAddress((void**)&bias, sc_bias);

    const int FLASH_SMEM = (6 * FT) * 2 + (2 * FT + 192) * 4;  // 92928 B
    cudaFuncSetAttribute(flash16, cudaFuncAttributeMaxDynamicSharedMemorySize, FLASH_SMEM);
    cudaFuncSetAttribute(gemm_h, cudaFuncAttributeMaxDynamicSharedMemorySize, GSMEM);

    const int M = T_TOK;
    dim3 thr(256);

    // 1-5: norm + packing (launch #6 = QKV GEMM gets profiled by ncu -s 5)
    rmsnorm_kernel<<<M, 256>>>(x, ln1, hh);
    pack_bias<<<8, 256>>>(bq, bk, bv, bias);
    pack_qkv<<<8192, 256>>>(wq, wk, wv, w + OFF_QKV);
    pack_gu<<<65536, 256>>>(w_gate, w_up, we_gate, we_up, w + OFF_GU);
    f2h_kernel<<<512, 256>>>(wo, w + OFF_WO);

    // 6: QKV projection -> fp16 qkv (bias folded)
    gemm_h<<<dim3(16, 64), thr, GSMEM>>>(hh, w + OFF_QKV, nullptr, qkv,
                                         M, 2048, 1024, bias, nullptr, 0);

    pack_down<<<32768, 256>>>(w_down, we_down, w + OFF_DN);
    rope_table<<<256, 256>>>(ct, st);
    rope_apply<<<16384, 256>>>(qkv, 16, 0,    ct, st);
    rope_apply<<< 8192, 256>>>(qkv,  8, 1024, ct, st);

    flash16<<<dim3(32, 16, 4), 256, FLASH_SMEM>>>(qkv, aoh);

    // out = x + attn @ Wo
    gemm_h<<<dim3(8, 64), thr, GSMEM>>>(aoh, w + OFF_WO, out, nullptr,
                                        M, 1024, 1024, nullptr, x, 0);

    rmsnorm_kernel<<<M, 256>>>(out, ln2, hh);

    // fused gate|up|egate|eup
    gemm_h<<<dim3(128, 64), thr, GSMEM>>>(hh, w + OFF_GU, nullptr, gu,
                                          M, 16384, 1024, nullptr, nullptr, 0);
    swiglu2<<<131072, 256>>>(gu, act, emask);

    // fused down: out += act @ [Wd ; Ed]
    gemm_h<<<dim3(8, 64), thr, GSMEM>>>(act, w + OFF_DN, out, nullptr,
                                        M, 1024, 8192, nullptr, nullptr, 1);
}